// round 12
// baseline (speedup 1.0000x reference)
#include <cuda_runtime.h>

#define N 384
#define D 512
#define MARGIN 0.5f
#define EPS 1e-6f
#define BLK 384
#define NWARP (BLK / 32)

// Finalize scratch; zero-initialized at load, winner resets each launch so
// graph replays start clean.
__device__ float g_acc;
__device__ int   g_cnt;

__device__ __forceinline__ float warp_sum(float v) {
#pragma unroll
    for (int o = 16; o; o >>= 1) v += __shfl_xor_sync(0xffffffffu, v, o);
    return v;
}

__global__ __launch_bounds__(BLK) void triplet_fused_kernel(
    const float* __restrict__ features,
    const int*   __restrict__ labels,
    const int*   __restrict__ levels,
    float*       __restrict__ out) {
    __shared__ int   s_list[N];      // [0..npos) positives, [npos..npos+nneg) negatives
    __shared__ float s_distc[N];     // distance per compacted ordinal
    __shared__ int   s_wpos[NWARP];  // per-warp positive counts
    __shared__ int   s_wneg[NWARP];  // per-warp negative counts

    const int i    = blockIdx.x;
    const int t    = threadIdx.x;
    const int wid  = t >> 5;
    const int lane = t & 31;

    // Anchor row -> registers FIRST: overlaps the fetch with label loads,
    // ballots and both compaction barriers. L1-broadcast across warps.
    const float4* __restrict__ fi = (const float4*)(features + i * D);
    const float4 a0 = fi[lane];
    const float4 a1 = fi[32 + lane];
    const float4 a2 = fi[64 + lane];
    const float4 a3 = fi[96 + lane];

    const int lab_i = labels[i];     // broadcast: one L2 transaction
    const int lev_i = levels[i];
    const int lab_t = labels[t];     // coalesced
    const int lev_t = levels[t];

    const bool same   = (t != i) && (lab_t == lab_i);
    const bool is_pos = same && (lev_t == lev_i);
    const bool is_neg = same && !is_pos;

    const unsigned bal_pos = __ballot_sync(0xffffffffu, is_pos);
    const unsigned bal_neg = __ballot_sync(0xffffffffu, is_neg);
    if (lane == 0) {
        s_wpos[wid] = __popc(bal_pos);
        s_wneg[wid] = __popc(bal_neg);
    }
    __syncthreads();

    // Register prefix over 12 warp counts (paid once).
    int base_p = 0, base_n = 0, npos = 0, nneg = 0;
#pragma unroll
    for (int w = 0; w < NWARP; w++) {
        const int cp = s_wpos[w], cn = s_wneg[w];
        if (w < wid) { base_p += cp; base_n += cn; }
        npos += cp;
        nneg += cn;
    }
    if (is_pos) s_list[base_p + __popc(bal_pos & ((1u << lane) - 1u))] = t;
    if (is_neg) s_list[npos + base_n + __popc(bal_neg & ((1u << lane) - 1u))] = t;
    __syncthreads();

    // ---- distances: warps round-robin over the compacted list (balanced) ----
    const int nsame = npos + nneg;
    for (int m = wid; m < nsame; m += NWARP) {
        const int j = s_list[m];
        const float4* __restrict__ fj = (const float4*)(features + j * D);
        const float4 b0 = fj[lane];
        const float4 b1 = fj[32 + lane];
        const float4 b2 = fj[64 + lane];
        const float4 b3 = fj[96 + lane];

        // Two accumulators: halves the serial fma dependency chain.
        float acc0 = 0.0f, acc1 = 0.0f, d;
        d = a0.x - b0.x + EPS; acc0 = fmaf(d, d, acc0);  // torch eps convention
        d = a0.y - b0.y + EPS; acc1 = fmaf(d, d, acc1);
        d = a0.z - b0.z + EPS; acc0 = fmaf(d, d, acc0);
        d = a0.w - b0.w + EPS; acc1 = fmaf(d, d, acc1);
        d = a1.x - b1.x + EPS; acc0 = fmaf(d, d, acc0);
        d = a1.y - b1.y + EPS; acc1 = fmaf(d, d, acc1);
        d = a1.z - b1.z + EPS; acc0 = fmaf(d, d, acc0);
        d = a1.w - b1.w + EPS; acc1 = fmaf(d, d, acc1);
        d = a2.x - b2.x + EPS; acc0 = fmaf(d, d, acc0);
        d = a2.y - b2.y + EPS; acc1 = fmaf(d, d, acc1);
        d = a2.z - b2.z + EPS; acc0 = fmaf(d, d, acc0);
        d = a2.w - b2.w + EPS; acc1 = fmaf(d, d, acc1);
        d = a3.x - b3.x + EPS; acc0 = fmaf(d, d, acc0);
        d = a3.y - b3.y + EPS; acc1 = fmaf(d, d, acc1);
        d = a3.z - b3.z + EPS; acc0 = fmaf(d, d, acc0);
        d = a3.w - b3.w + EPS; acc1 = fmaf(d, d, acc1);

        const float tot = warp_sum(acc0 + acc1);
        if (lane == 0) s_distc[m] = sqrtf(tot);
    }
    __syncthreads();

    // ---- warp 0: full hinge (npos*nneg terms, lane-strided) + finalize ----
    if (wid == 0) {
        float acc = 0.0f;
        const int npair = npos * nneg;
        for (int p = lane; p < npair; p += 32) {
            const int a = p / nneg;          // positive ordinal
            const int q = p - a * nneg;      // negative ordinal
            acc += fmaxf(s_distc[a] - s_distc[npos + q] + MARGIN, 0.0f);
        }
        acc = warp_sum(acc);

        if (lane == 0) {
            float contrib = 0.0f;
            if (npair > 0) contrib = acc / (float)npair * (1.0f / (float)N);
            atomicAdd(&g_acc, contrib);      // no return -> REDG
            __threadfence();
            if (atomicAdd(&g_cnt, 1) == (int)gridDim.x - 1) {
                g_cnt = 0;
                out[0] = atomicExch(&g_acc, 0.0f);  // read + reset for replay
            }
        }
    }
}

extern "C" void kernel_launch(void* const* d_in, const int* in_sizes, int n_in,
                              void* d_out, int out_size) {
    const float* features = (const float*)d_in[0];
    const int*   labels   = (const int*)d_in[1];
    const int*   levels   = (const int*)d_in[2];
    float* out = (float*)d_out;

    triplet_fused_kernel<<<N, BLK>>>(features, labels, levels, out);
}